// round 17
// baseline (speedup 1.0000x reference)
#include <cuda_runtime.h>
#include <cuda_bf16.h>
#include <cstdint>

#define NNODES 100000
#define NEDGES 1600000
#define DIM    128
#define SCANB  1024
#define NBLK   ((NNODES + SCANB - 1) / SCANB)   // 98
#define SWROW  129                              // smem row stride (mod 32 == 1)

#define NCHUNK     4
#define CHUNK_BLK  391                          // gemm blocks per chunk (x64 nodes)
#define CHUNK_N    (CHUNK_BLK * 64)             // 25024 nodes per chunk

typedef unsigned long long u64;

// ---------------- scratch (alloc-free rule: __device__ globals) -------------
// g_deg: zero-initialized at module load; fill_kernel re-zeroes it each call.
__device__ float g_agg[(size_t)NNODES * DIM];
__device__ int   g_deg[NNODES];
__device__ int   g_incl[NNODES];
__device__ int   g_off[NNODES + 1];
__device__ int   g_cur[NNODES];
__device__ int   g_csr[NEDGES];
__device__ int   g_bsum[128];
__device__ int   g_bofs[128];

// ---------------------------------------------------------------------------
// packed fp32x2 helpers
// ---------------------------------------------------------------------------
__device__ __forceinline__ u64 ffma2(u64 a, u64 b, u64 c) {
    u64 d;
    asm("fma.rn.f32x2 %0, %1, %2, %3;" : "=l"(d) : "l"(a), "l"(b), "l"(c));
    return d;
}
__device__ __forceinline__ u64 pk2(float lo, float hi) {
    u64 r;
    asm("mov.b64 %0, {%1, %2};" : "=l"(r) : "f"(lo), "f"(hi));
    return r;
}

// ---------------------------------------------------------------------------
// CSR build (R9, measured good)
// ---------------------------------------------------------------------------
__global__ void hist_kernel(const int* __restrict__ ei) {
    int e = blockIdx.x * blockDim.x + threadIdx.x;
    if (e < NEDGES) atomicAdd(&g_deg[__ldg(ei + NEDGES + e)], 1);
}

__global__ void scan1_kernel() {
    __shared__ int sm[SCANB];
    int i = blockIdx.x * SCANB + threadIdx.x;
    int v = (i < NNODES) ? g_deg[i] : 0;
    sm[threadIdx.x] = v;
    __syncthreads();
#pragma unroll
    for (int ofs = 1; ofs < SCANB; ofs <<= 1) {
        int t = (threadIdx.x >= ofs) ? sm[threadIdx.x - ofs] : 0;
        __syncthreads();
        sm[threadIdx.x] += t;
        __syncthreads();
    }
    if (i < NNODES) g_incl[i] = sm[threadIdx.x];
    if (threadIdx.x == SCANB - 1) g_bsum[blockIdx.x] = sm[SCANB - 1];
}

__global__ void scan2_kernel() {
    __shared__ int sm[128];
    int t = threadIdx.x;
    int v = (t < NBLK) ? g_bsum[t] : 0;
    sm[t] = v;
    __syncthreads();
#pragma unroll
    for (int ofs = 1; ofs < 128; ofs <<= 1) {
        int u = (t >= ofs) ? sm[t - ofs] : 0;
        __syncthreads();
        sm[t] += u;
        __syncthreads();
    }
    if (t < NBLK) g_bofs[t] = sm[t] - v;    // exclusive
}

__global__ void scan3_kernel() {
    int i = blockIdx.x * blockDim.x + threadIdx.x;
    if (i < NNODES) {
        int off = g_incl[i] - g_deg[i] + g_bofs[i >> 10];
        g_off[i] = off;
        g_cur[i] = off;
    }
    if (i == 0) g_off[NNODES] = NEDGES;
}

__global__ void fill_kernel(const int* __restrict__ ei) {
    int e = blockIdx.x * blockDim.x + threadIdx.x;
    if (e < NEDGES) {
        int dst = __ldg(ei + NEDGES + e);
        int p = atomicAdd(&g_cur[dst], 1);
        g_csr[p] = __ldg(ei + e);
    }
    if (e < NNODES) g_deg[e] = 0;   // restore invariant for next replay
}

// ---------------------------------------------------------------------------
// Aggregation (R6/R9 body — measured best), chunked over [lo, hi).
// One warp per node, lane l owns dims [4l, 4l+4).
// ---------------------------------------------------------------------------
__global__ __launch_bounds__(256)
void agg_kernel(const float* __restrict__ x, int lo, int hi) {
    int w    = lo + ((blockIdx.x * blockDim.x + threadIdx.x) >> 5);
    int lane = threadIdx.x & 31;
    if (w >= hi) return;

    const float4* X = reinterpret_cast<const float4*>(x);
    int s = g_off[w];
    int e = g_off[w + 1];

    float4 acc = __ldg(X + (size_t)w * 32 + lane);   // self term (eps=0)

    for (int base = s; base < e; base += 32) {
        int idx = base + lane;
        int my  = (idx < e) ? __ldg(g_csr + idx) : 0;
        int nv  = min(32, e - base);
#pragma unroll 4
        for (int j = 0; j < nv; ++j) {
            int src  = __shfl_sync(0xffffffffu, my, j);
            float4 v = __ldg(X + (size_t)src * 32 + lane);
            acc.x += v.x; acc.y += v.y; acc.z += v.z; acc.w += v.w;
        }
    }
    reinterpret_cast<float4*>(g_agg)[(size_t)w * 32 + lane] = acc;
}

// ---------------------------------------------------------------------------
// GEMM (R9 body — measured good), chunked: block b covers nodes
// [node_lo + b*64, +64). out[n][o] = bias[o] + sum_k H[n][k]*W[o][k].
// ---------------------------------------------------------------------------
__global__ __launch_bounds__(128, 2)
void gemm_kernel(const float* __restrict__ H,
                 const float* __restrict__ W,
                 const float* __restrict__ bias,
                 float* __restrict__ out, int node_lo) {
    extern __shared__ float smf[];
    float* Ws = smf;                   // [128][SWROW]
    float* Hs = smf + DIM * SWROW;     // [64][SWROW]

    const int tid   = threadIdx.x;
    const int node0 = node_lo + blockIdx.x * 64;

    for (int i = tid; i < DIM * DIM / 4; i += 128) {
        int o  = i >> 5;
        int k4 = (i & 31) << 2;
        float4 w = __ldg(reinterpret_cast<const float4*>(W) + i);
        float* p = Ws + o * SWROW + k4;
        p[0] = w.x; p[1] = w.y; p[2] = w.z; p[3] = w.w;
    }
    for (int i = tid; i < 64 * DIM / 4; i += 128) {
        int n  = i >> 5;
        int k4 = (i & 31) << 2;
        int node = node0 + n;
        float4 h = make_float4(0.f, 0.f, 0.f, 0.f);
        if (node < NNODES)
            h = __ldg(reinterpret_cast<const float4*>(H) + (size_t)node * 32 + (k4 >> 2));
        float* p = Hs + n * SWROW + k4;
        p[0] = h.x; p[1] = h.y; p[2] = h.z; p[3] = h.w;
    }
    __syncthreads();

    const int tx = tid >> 3;
    const int ty = tid & 7;
    const int o0 = tx * 8;
    const int n0 = ty * 8;

    const float* Wb = Ws + o0 * SWROW;
    const float* Hb = Hs + n0 * SWROW;

    u64 acc[8][4];
    {
        float4 b0 = __ldg(reinterpret_cast<const float4*>(bias + o0));
        float4 b1 = __ldg(reinterpret_cast<const float4*>(bias + o0 + 4));
        u64 bp[4] = { pk2(b0.x, b0.y), pk2(b0.z, b0.w),
                      pk2(b1.x, b1.y), pk2(b1.z, b1.w) };
#pragma unroll
        for (int i = 0; i < 8; ++i)
#pragma unroll
            for (int j = 0; j < 4; ++j) acc[i][j] = bp[j];
    }

#pragma unroll 4
    for (int k = 0; k < DIM; ++k) {
        float w[8], h[8];
#pragma unroll
        for (int i = 0; i < 8; ++i) w[i] = Wb[i * SWROW + k];
#pragma unroll
        for (int i = 0; i < 8; ++i) h[i] = Hb[i * SWROW + k];
        u64 wp[4] = { pk2(w[0], w[1]), pk2(w[2], w[3]),
                      pk2(w[4], w[5]), pk2(w[6], w[7]) };
#pragma unroll
        for (int i = 0; i < 8; ++i) {
            u64 hd = pk2(h[i], h[i]);
#pragma unroll
            for (int j = 0; j < 4; ++j)
                acc[i][j] = ffma2(hd, wp[j], acc[i][j]);
        }
    }

#pragma unroll
    for (int i = 0; i < 8; ++i) {
        int node = node0 + n0 + i;
        if (node < NNODES) {
            ulonglong2* orow = reinterpret_cast<ulonglong2*>(out + (size_t)node * DIM + o0);
            orow[0] = make_ulonglong2(acc[i][0], acc[i][1]);
            orow[1] = make_ulonglong2(acc[i][2], acc[i][3]);
        }
    }
}

// ---------------------------------------------------------------------------
// Launch: CSR on the origin stream, then fork into two streams:
//   sA: agg chunks (memory-bound)   sB: gemm chunks (fma-bound)
// gemm chunk c waits only on agg chunk c -> GEMM hides under the next agg.
// Full join at the layer boundary (agg2 gathers arbitrary hid rows).
// ---------------------------------------------------------------------------
extern "C" void kernel_launch(void* const* d_in, const int* in_sizes, int n_in,
                              void* d_out, int out_size) {
    const float* x  = (const float*)d_in[0];
    const int*   ei = (const int*)  d_in[1];
    const float* W1 = (const float*)d_in[2];
    const float* b1 = (const float*)d_in[3];
    const float* W2 = (const float*)d_in[4];
    const float* b2 = (const float*)d_in[5];

    float* out = (float*)d_out;
    float* hid = (float*)d_out + (size_t)NNODES * DIM;

    const int smem = (DIM + 64) * SWROW * (int)sizeof(float);   // 99072 B

    static bool inited = false;
    static cudaStream_t sA, sB;
    static cudaEvent_t evFork, evL1, evEnd;
    static cudaEvent_t evA[2 * NCHUNK];
    if (!inited) {
        cudaFuncSetAttribute(gemm_kernel,
                             cudaFuncAttributeMaxDynamicSharedMemorySize, smem);
        cudaStreamCreateWithFlags(&sA, cudaStreamNonBlocking);
        cudaStreamCreateWithFlags(&sB, cudaStreamNonBlocking);
        cudaEventCreateWithFlags(&evFork, cudaEventDisableTiming);
        cudaEventCreateWithFlags(&evL1,   cudaEventDisableTiming);
        cudaEventCreateWithFlags(&evEnd,  cudaEventDisableTiming);
        for (int i = 0; i < 2 * NCHUNK; ++i)
            cudaEventCreateWithFlags(&evA[i], cudaEventDisableTiming);
        inited = true;
    }

    float* agg;
    cudaGetSymbolAddress((void**)&agg, g_agg);

    const int nb_nodes = (NNODES + 255) / 256;
    const int nb_edges = (NEDGES + 255) / 256;

    // ---- CSR build on origin stream ----
    hist_kernel<<<nb_edges, 256>>>(ei);
    scan1_kernel<<<NBLK, SCANB>>>();
    scan2_kernel<<<1, 128>>>();
    scan3_kernel<<<nb_nodes, 256>>>();
    fill_kernel<<<nb_edges, 256>>>(ei);

    // ---- fork ----
    cudaEventRecord(evFork, 0);
    cudaStreamWaitEvent(sA, evFork, 0);
    cudaStreamWaitEvent(sB, evFork, 0);

    // ---- Layer 1 (pipelined chunks) ----
    for (int c = 0; c < NCHUNK; ++c) {
        int lo = c * CHUNK_N;
        int hi = (c == NCHUNK - 1) ? NNODES : lo + CHUNK_N;
        int nb = ((hi - lo) * 32 + 255) / 256;
        int gb = (hi - lo + 63) / 64;
        agg_kernel<<<nb, 256, 0, sA>>>(x, lo, hi);
        cudaEventRecord(evA[c], sA);
        cudaStreamWaitEvent(sB, evA[c], 0);
        gemm_kernel<<<gb, 128, smem, sB>>>(agg, W1, b1, hid, lo);
    }
    cudaEventRecord(evL1, sB);
    cudaStreamWaitEvent(sA, evL1, 0);   // agg2 needs ALL of hid

    // ---- Layer 2 (pipelined chunks) ----
    for (int c = 0; c < NCHUNK; ++c) {
        int lo = c * CHUNK_N;
        int hi = (c == NCHUNK - 1) ? NNODES : lo + CHUNK_N;
        int nb = ((hi - lo) * 32 + 255) / 256;
        int gb = (hi - lo + 63) / 64;
        agg_kernel<<<nb, 256, 0, sA>>>(hid, lo, hi);
        cudaEventRecord(evA[NCHUNK + c], sA);
        cudaStreamWaitEvent(sB, evA[NCHUNK + c], 0);
        gemm_kernel<<<gb, 128, smem, sB>>>(agg, W2, b2, out, lo);
    }

    // ---- join back to origin stream ----
    cudaEventRecord(evEnd, sB);
    cudaStreamWaitEvent(0, evEnd, 0);
}